// round 17
// baseline (speedup 1.0000x reference)
#include <cuda_runtime.h>
#include <cuda_fp16.h>
#include <math.h>

#define B_ 64
#define T_ 1024
#define D_ 512
#define U_ 1024
#define BT (B_ * T_)

// ---------------- device scratch (no allocation allowed) ----------------
__device__ __align__(128) __half g_fhi[BT * D_];   // 64 MB (written by score)
__device__ __align__(128) __half g_w1t[U_ * D_];   // [n][k], 1 MB
__device__ float g_projh[B_ * U_];
__device__ float g_logits[BT];     // complete logits (no partials)

// ---------------- PTX helpers ----------------
__device__ __forceinline__ unsigned smem_u32(const void* p) {
    unsigned a;
    asm("{ .reg .u64 t; cvta.to.shared.u64 t, %1; cvt.u32.u64 %0, t; }"
        : "=r"(a) : "l"(p));
    return a;
}
__device__ __forceinline__ void cpa16(unsigned dst, const void* src) {
    asm volatile("cp.async.cg.shared.global [%0], [%1], 16;" :: "r"(dst), "l"(src));
}
__device__ __forceinline__ void cpa_commit() { asm volatile("cp.async.commit_group;"); }
__device__ __forceinline__ void ldsm4(unsigned addr, unsigned& r0, unsigned& r1,
                                      unsigned& r2, unsigned& r3) {
    asm volatile("ldmatrix.sync.aligned.m8n8.x4.shared.b16 {%0,%1,%2,%3}, [%4];"
                 : "=r"(r0), "=r"(r1), "=r"(r2), "=r"(r3) : "r"(addr));
}
__device__ __forceinline__ void mma16816(float* c, unsigned a0, unsigned a1,
                                         unsigned a2, unsigned a3,
                                         unsigned b0, unsigned b1) {
    asm volatile(
        "mma.sync.aligned.m16n8k16.row.col.f32.f16.f16.f32 "
        "{%0,%1,%2,%3}, {%4,%5,%6,%7}, {%8,%9}, {%0,%1,%2,%3};"
        : "+f"(c[0]), "+f"(c[1]), "+f"(c[2]), "+f"(c[3])
        : "r"(a0), "r"(a1), "r"(a2), "r"(a3), "r"(b0), "r"(b1));
}
// fast tanh: 1 - 2/(e^{2x}+1). abs err ~2e-7.
__device__ __forceinline__ float ftanh(float x) {
    float e = __expf(2.0f * x);
    return 1.0f - __fdividef(2.0f, e + 1.0f);
}
__device__ __forceinline__ uint2 pack4h(float4 v) {
    uint2 hw;
    hw.x = (unsigned)__half_as_ushort(__float2half_rn(v.x)) |
           ((unsigned)__half_as_ushort(__float2half_rn(v.y)) << 16);
    hw.y = (unsigned)__half_as_ushort(__float2half_rn(v.z)) |
           ((unsigned)__half_as_ushort(__float2half_rn(v.w)) << 16);
    return hw;
}

// ---------------- smem layout for score kernel (2 CTAs/SM) ----------------
// A persistent: 8 chunk-tiles (64 rows x 64 k fp16, swizzled 128B rows) = 64KB
#define OFF_B   65536          // 2 x 16KB B double buffer
#define OFF_PH  98304          // 1024 floats
#define OFF_V   102400         // 1024 floats
#define OFF_RED 106496         // 64 x 4 floats
#define SMEM_TOTAL_S 107520

// ---------------------------------------------------------------------------
// prep kernel: W1 transpose->fp16 + proj_h GEMV   (544 blocks)
// ---------------------------------------------------------------------------
#define NW_BLK 512                   // (U/32) x (D/32)
#define NP_BLK 32                    // (U/256) x (B/8)
__global__ void __launch_bounds__(256)
prep_kernel(const float* __restrict__ W1, const float* __restrict__ hidden,
            const float* __restrict__ W2, const float* __restrict__ W2b) {
    __shared__ __align__(16) char sbuf[16384];
    const int bid = blockIdx.x;
    const int tid = threadIdx.x;

    if (bid < NW_BLK) {
        float (*tile)[33] = (float(*)[33])sbuf;
        const int n0 = (bid & 31) * 32, k0 = (bid >> 5) * 32;
        const int tx = tid & 31, ty = tid >> 5;
        for (int r = ty; r < 32; r += 8)
            tile[r][tx] = W1[(size_t)(k0 + r) * U_ + n0 + tx];
        __syncthreads();
        for (int rr = ty; rr < 32; rr += 8)
            g_w1t[(size_t)(n0 + rr) * D_ + k0 + tx] = __float2half_rn(tile[tx][rr]);
    } else {
        float (*hs)[D_] = (float(*)[D_])sbuf;
        const int pb = bid - NW_BLK;
        const int u = (pb & 3) * 256 + tid;
        const int b0 = (pb >> 2) * 8;
#pragma unroll
        for (int i = 0; i < 4; i++)
            ((float4*)hs)[tid + i * 256] =
                ((const float4*)(hidden + (size_t)b0 * D_))[tid + i * 256];
        __syncthreads();
        float acc[8];
#pragma unroll
        for (int i = 0; i < 8; i++) acc[i] = 0.f;
#pragma unroll 4
        for (int k = 0; k < D_; k++) {
            float w = W2[(size_t)k * U_ + u];
#pragma unroll
            for (int bb = 0; bb < 8; bb++) acc[bb] += hs[bb][k] * w;
        }
        float bias = W2b[u];
#pragma unroll
        for (int bb = 0; bb < 8; bb++)
            g_projh[(size_t)(b0 + bb) * U_ + u] = acc[bb] + bias;
    }
}

// ---------------------------------------------------------------------------
// score kernel: persistent-A fp16 GEMM over full U, fused fp32->fp16 convert
// grid 1024 (m-tiles of 64), 256 threads (8 warps 2x4, warp tile 32m x 32n)
// ---------------------------------------------------------------------------
__global__ void __launch_bounds__(256, 2)
score_kernel(const float* __restrict__ feat, const float* __restrict__ W1b,
             const float* __restrict__ Vw) {
    extern __shared__ __align__(1024) char smem[];
    const unsigned sbase = smem_u32(smem);
    const int tid = threadIdx.x;
    const int wid = tid >> 5, lid = tid & 31;
    const int wm = wid & 1, wn = wid >> 1;       // 2 x 4 warp grid, tile 32m x 32n
    const int bt0 = blockIdx.x * 64;
    const int b = blockIdx.x >> 4;
    float* shPh = (float*)(smem + OFF_PH);
    float* shV  = (float*)(smem + OFF_V);
    float (*red)[4] = (float(*)[4])(smem + OFF_RED);

    // ---- preload proj_h + W1_b and V (full 1024) ----
#pragma unroll
    for (int i = 0; i < 4; i++) {
        int idx = tid + i * 256;
        shPh[idx] = g_projh[(size_t)b * U_ + idx] + W1b[idx];
        shV[idx]  = Vw[idx];
    }

    // ---- A prologue: load fp32 feat, convert, store swizzled smem + g_fhi ----
    // 8192 float4 granules; thread handles g = tid + i*256, i<32, in 4 batches of 8
#pragma unroll
    for (int p = 0; p < 4; p++) {
        float4 v[8];
#pragma unroll
        for (int j = 0; j < 8; j++) {
            int g = tid + (p * 8 + j) * 256;
            int row = g >> 7, kg = g & 127;
            v[j] = __ldcs(((const float4*)feat) + (size_t)(bt0 + row) * 128 + kg);
        }
#pragma unroll
        for (int j = 0; j < 8; j++) {
            int g = tid + (p * 8 + j) * 256;
            int row = g >> 7, kg = g & 127;
            uint2 hw = pack4h(v[j]);
            int kgc = kg & 15;
            unsigned dst = (unsigned)((kg >> 4) * 8192 + row * 128 +
                           (((kgc >> 1) ^ (row & 7)) * 16) + (kgc & 1) * 8);
            *(uint2*)(smem + dst) = hw;
            ((uint2*)g_fhi)[(size_t)(bt0 + row) * 128 + kg] = hw;
        }
    }

    // ---- B cp.async loop-invariant offsets (4 granules/thread per chunk) ----
    unsigned b_src0, b_dst0;
    {
        int row = tid >> 3, c16 = tid & 7;
        b_src0 = (unsigned)(row * D_ + c16 * 8);        // fp16 units
        b_dst0 = row * 128 + ((c16 ^ (row & 7)) * 16);
    }

    // ---- ldmatrix bases ----
    const int lrow = lid & 15;
    const int lch  = lid >> 4;
    unsigned abase0, bbase0;
    {
        int row = wm * 32 + lrow;
        abase0 = row * 128 + ((lch ^ (row & 7)) * 16);
        int rowb = wn * 32 + lrow;
        bbase0 = rowb * 128 + ((lch ^ (rowb & 7)) * 16);
    }

    __syncthreads();   // A tiles ready

    // prefetch B chunk 0 (nq=0, kc=0)
#pragma unroll
    for (int i = 0; i < 4; i++)
        cpa16(sbase + OFF_B + b_dst0 + i * 4096, g_w1t + b_src0 + i * 16384);
    cpa_commit();

    float p0[2], p1[2];
    p0[0] = p0[1] = p1[0] = p1[1] = 0.f;

    for (int nq = 0; nq < 8; nq++) {
        float Cr[2][4][4];
#pragma unroll
        for (int mt = 0; mt < 2; mt++)
#pragma unroll
            for (int nt = 0; nt < 4; nt++)
#pragma unroll
                for (int j = 0; j < 4; j++) Cr[mt][nt][j] = 0.f;

        for (int kc = 0; kc < 8; kc++) {
            const int ci = nq * 8 + kc;
            asm volatile("cp.async.wait_group 0;" ::: "memory");
            __syncthreads();
            if (ci < 63) {
                const int cin = ci + 1;
                const __half* src = g_w1t + (size_t)((cin >> 3) * 128) * D_ + (cin & 7) * 64;
                const unsigned dstb = sbase + OFF_B + ((cin & 1) ? 16384u : 0u);
#pragma unroll
                for (int i = 0; i < 4; i++)
                    cpa16(dstb + b_dst0 + i * 4096, src + b_src0 + i * 16384);
                cpa_commit();
            }
            const unsigned Ab = sbase + kc * 8192;
            const unsigned Bb = sbase + OFF_B + ((ci & 1) ? 16384u : 0u);
#pragma unroll
            for (int kk = 0; kk < 4; kk++) {
                const unsigned kx = kk << 5;
                unsigned bf[4][2];
                {
                    unsigned t0, t1, t2, t3, u0, u1, u2, u3;
                    ldsm4(Bb + (bbase0 ^ kx), t0, t1, t2, t3);
                    ldsm4(Bb + ((bbase0 + 2048) ^ kx), u0, u1, u2, u3);
                    bf[0][0] = t0; bf[0][1] = t2;
                    bf[1][0] = t1; bf[1][1] = t3;
                    bf[2][0] = u0; bf[2][1] = u2;
                    bf[3][0] = u1; bf[3][1] = u3;
                }
                unsigned ah[2][4];
#pragma unroll
                for (int mt = 0; mt < 2; mt++)
                    ldsm4(Ab + ((abase0 + mt * 2048) ^ kx),
                          ah[mt][0], ah[mt][1], ah[mt][2], ah[mt][3]);
#pragma unroll
                for (int mt = 0; mt < 2; mt++)
#pragma unroll
                    for (int nt = 0; nt < 4; nt++)
                        mma16816(Cr[mt][nt], ah[mt][0], ah[mt][1], ah[mt][2], ah[mt][3],
                                 bf[nt][0], bf[nt][1]);
            }
        }
        // ---- epilogue for this nq: tanh + V-dot, accumulate ----
#pragma unroll
        for (int mt = 0; mt < 2; mt++)
#pragma unroll
            for (int nt = 0; nt < 4; nt++) {
                int nc = nq * 128 + wn * 32 + nt * 8 + (lid & 3) * 2;
                float ph0 = shPh[nc], ph1 = shPh[nc + 1];
                float v0 = shV[nc], v1 = shV[nc + 1];
                p0[mt] += ftanh(Cr[mt][nt][0] + ph0) * v0
                        + ftanh(Cr[mt][nt][1] + ph1) * v1;
                p1[mt] += ftanh(Cr[mt][nt][2] + ph0) * v0
                        + ftanh(Cr[mt][nt][3] + ph1) * v1;
            }
    }

    // ---- reduce logits: quad shfl + smem across wn ----
#pragma unroll
    for (int mt = 0; mt < 2; mt++) {
        p0[mt] += __shfl_xor_sync(0xFFFFFFFFu, p0[mt], 1);
        p0[mt] += __shfl_xor_sync(0xFFFFFFFFu, p0[mt], 2);
        p1[mt] += __shfl_xor_sync(0xFFFFFFFFu, p1[mt], 1);
        p1[mt] += __shfl_xor_sync(0xFFFFFFFFu, p1[mt], 2);
    }
    if ((lid & 3) == 0) {
#pragma unroll
        for (int mt = 0; mt < 2; mt++) {
            int rl = wm * 32 + mt * 16 + (lid >> 2);
            red[rl][wn] = p0[mt];
            red[rl + 8][wn] = p1[mt];
        }
    }
    __syncthreads();
    if (tid < 64)
        g_logits[bt0 + tid] = red[tid][0] + red[tid][1] + red[tid][2] + red[tid][3];
}

// ---------------------------------------------------------------------------
// fused softmax + context kernel: grid (B_, D/128), 1024 threads
// ---------------------------------------------------------------------------
__global__ void __launch_bounds__(1024)
softctx_kernel(const float* __restrict__ Vb, float* __restrict__ out) {
    __shared__ float ws[T_];
    __shared__ float rbuf[32];
    __shared__ float red[32][128];
    const int b = blockIdx.x;
    const int d0 = blockIdx.y * 128;
    const int tid = threadIdx.x;
    const int wid = tid >> 5, lid = tid & 31;

    // ---- softmax over T (each thread owns one logit) ----
    float l = Vb[0] + g_logits[b * T_ + tid];
    float mx = l;
#pragma unroll
    for (int s = 16; s > 0; s >>= 1) mx = fmaxf(mx, __shfl_xor_sync(~0u, mx, s));
    if (lid == 0) rbuf[wid] = mx;
    __syncthreads();
    if (tid < 32) {
        float m = rbuf[tid];
#pragma unroll
        for (int s = 16; s > 0; s >>= 1) m = fmaxf(m, __shfl_xor_sync(~0u, m, s));
        rbuf[tid] = m;
    }
    __syncthreads();
    mx = rbuf[0];
    float e = __expf(l - mx);
    float ssum = e;
#pragma unroll
    for (int s = 16; s > 0; s >>= 1) ssum += __shfl_xor_sync(~0u, ssum, s);
    __syncthreads();
    if (lid == 0) rbuf[wid] = ssum;
    __syncthreads();
    if (tid < 32) {
        float m = rbuf[tid];
#pragma unroll
        for (int s = 16; s > 0; s >>= 1) m += __shfl_xor_sync(~0u, m, s);
        rbuf[tid] = m;
    }
    __syncthreads();
    const float w = e * __fdividef(1.0f, rbuf[0]);
    ws[tid] = w;
    if (blockIdx.y == 0) out[B_ * D_ + b * T_ + tid] = w;
    __syncthreads();

    // ---- context: 32 T-splits x 32 d-quads ----
    const int dl = tid & 31;
    const int tq = tid >> 5;
    const __half* fb = g_fhi + (size_t)b * T_ * D_ + (size_t)tq * 32 * D_ + d0 + dl * 4;
    const float* wq = ws + tq * 32;
    float4 acc = make_float4(0.f, 0.f, 0.f, 0.f);
#pragma unroll 8
    for (int t = 0; t < 32; t++) {
        float wv = wq[t];
        uint2 h = *(const uint2*)(fb + (size_t)t * D_);
        float2 f0 = __half22float2(*(const __half2*)&h.x);
        float2 f1 = __half22float2(*(const __half2*)&h.y);
        acc.x += wv * f0.x; acc.y += wv * f0.y;
        acc.z += wv * f1.x; acc.w += wv * f1.y;
    }
    red[tq][dl * 4 + 0] = acc.x;
    red[tq][dl * 4 + 1] = acc.y;
    red[tq][dl * 4 + 2] = acc.z;
    red[tq][dl * 4 + 3] = acc.w;
    __syncthreads();
    if (tid < 128) {
        float s = 0.f;
#pragma unroll
        for (int q = 0; q < 32; q++) s += red[q][tid];
        out[b * D_ + d0 + tid] = s;
    }
}

// ---------------------------------------------------------------------------
extern "C" void kernel_launch(void* const* d_in, const int* in_sizes, int n_in,
                              void* d_out, int out_size) {
    const float* feat   = (const float*)d_in[0];
    const float* hidden = (const float*)d_in[1];
    const float* W1w    = (const float*)d_in[2];
    const float* W1b    = (const float*)d_in[3];
    const float* W2w    = (const float*)d_in[4];
    const float* W2b    = (const float*)d_in[5];
    const float* Vw     = (const float*)d_in[6];
    const float* Vb     = (const float*)d_in[7];
    float* out = (float*)d_out;

    static bool attr_set = false;
    if (!attr_set) {
        cudaFuncSetAttribute(score_kernel, cudaFuncAttributeMaxDynamicSharedMemorySize,
                             SMEM_TOTAL_S);
        attr_set = true;
    }

    prep_kernel<<<NW_BLK + NP_BLK, 256>>>(W1w, hidden, W2w, W2b);
    score_kernel<<<BT / 64, 256, SMEM_TOTAL_S>>>(feat, W1b, Vw);
    softctx_kernel<<<dim3(B_, D_ / 128), 1024>>>(Vb, out);
}